// round 2
// baseline (speedup 1.0000x reference)
#include <cuda_runtime.h>

#define NBINS 2000
#define FRAC_SCALE 16777216.0f      /* 2^24 */
#define FRAC_INV   (1.0 / 16777216.0)
#define SUM_MASK   0xFFFFFFFFFFULL  /* low 40 bits */

// Persistent scratch (zero-initialized at module load; finalize kernel re-zeroes
// for the next graph replay, so no init kernel is needed).
__device__ unsigned long long g_bins[NBINS];
__device__ double g_neg;    // sum of exp(Yhat) over Y<0
__device__ double g_yhat;   // sum of Yhat over Y>0 (loss1)

// ---------------------------------------------------------------------------
// Pass 1: histogram exp(Yhat) by time bin for events; accumulate negatives.
// One u64 shared atomic per positive element: packed = (1<<40) | round(e*2^24)
// ---------------------------------------------------------------------------
__global__ void __launch_bounds__(512) surv_hist(
    const float* __restrict__ Yhat, const float* __restrict__ Y, int n)
{
    __shared__ unsigned long long sBins[NBINS];
    for (int i = threadIdx.x; i < NBINS; i += blockDim.x) sBins[i] = 0ULL;
    __syncthreads();

    float negAcc = 0.f, yhatAcc = 0.f;

    const int n4 = n >> 2;
    const float4* Yh4 = (const float4*)Yhat;
    const float4* Y4  = (const float4*)Y;
    const int stride = gridDim.x * blockDim.x;

    for (int i = blockIdx.x * blockDim.x + threadIdx.x; i < n4; i += stride) {
        float4 yh = Yh4[i];
        float4 yy = Y4[i];
        float hv[4] = {yh.x, yh.y, yh.z, yh.w};
        float yv[4] = {yy.x, yy.y, yy.z, yy.w};
        #pragma unroll
        for (int k = 0; k < 4; k++) {
            float e = expf(hv[k]);
            if (yv[k] > 0.f) {
                int t = (int)yv[k];                      // 1..2000
                t = (t < 1) ? 1 : (t > NBINS ? NBINS : t);
                unsigned long long q = __float2ull_rn(e * FRAC_SCALE);
                atomicAdd(&sBins[t - 1], (1ULL << 40) | q);
                yhatAcc += hv[k];
            } else {
                negAcc += e;
            }
        }
    }

    // scalar tail (N is a multiple of 4 here, but stay general)
    if (blockIdx.x == 0 && threadIdx.x == 0) {
        for (int i = n4 << 2; i < n; i++) {
            float e = expf(Yhat[i]);
            float y = Y[i];
            if (y > 0.f) {
                int t = (int)y;
                t = (t < 1) ? 1 : (t > NBINS ? NBINS : t);
                unsigned long long q = __float2ull_rn(e * FRAC_SCALE);
                atomicAdd(&sBins[t - 1], (1ULL << 40) | q);
                yhatAcc += Yhat[i];
            } else {
                negAcc += e;
            }
        }
    }

    __syncthreads();

    // Flush shared histogram to global (deterministic integer adds)
    for (int i = threadIdx.x; i < NBINS; i += blockDim.x) {
        unsigned long long v = sBins[i];
        if (v) atomicAdd(&g_bins[i], v);
    }

    // Block-reduce negAcc / yhatAcc, one double atomic per block
    #pragma unroll
    for (int d = 16; d; d >>= 1) {
        negAcc  += __shfl_down_sync(0xffffffffu, negAcc,  d);
        yhatAcc += __shfl_down_sync(0xffffffffu, yhatAcc, d);
    }
    __shared__ float wNeg[32], wYh[32];
    int lane = threadIdx.x & 31, wid = threadIdx.x >> 5;
    if (lane == 0) { wNeg[wid] = negAcc; wYh[wid] = yhatAcc; }
    __syncthreads();
    if (wid == 0) {
        int nw = blockDim.x >> 5;
        float a = (lane < nw) ? wNeg[lane] : 0.f;
        float b = (lane < nw) ? wYh[lane] : 0.f;
        #pragma unroll
        for (int d = 16; d; d >>= 1) {
            a += __shfl_down_sync(0xffffffffu, a, d);
            b += __shfl_down_sync(0xffffffffu, b, d);
        }
        if (lane == 0) {
            atomicAdd(&g_neg,  (double)a);
            atomicAdd(&g_yhat, (double)b);
        }
    }
}

// ---------------------------------------------------------------------------
// Pass 2: 2000-bin inclusive scan (double), loss2 = sum cnt[t]*log(P[t]),
// finalize output, then self-clean scratch for the next graph replay.
// ---------------------------------------------------------------------------
__global__ void __launch_bounds__(1024) surv_final(float* out, int out_size)
{
    const int tid = threadIdx.x;
    const int lane = tid & 31, wid = tid >> 5;

    double v0 = 0.0, v1 = 0.0;
    long long c0 = 0, c1 = 0;
    int b0 = 2 * tid, b1 = 2 * tid + 1;
    if (b0 < NBINS) {
        unsigned long long p = g_bins[b0];
        v0 = (double)(p & SUM_MASK) * FRAC_INV;
        c0 = (long long)(p >> 40);
    }
    if (b1 < NBINS) {
        unsigned long long p = g_bins[b1];
        v1 = (double)(p & SUM_MASK) * FRAC_INV;
        c1 = (long long)(p >> 40);
    }

    double pair = v0 + v1;

    // inclusive scan of `pair` across 1024 threads (warp shfl + warp totals)
    double x = pair;
    #pragma unroll
    for (int d = 1; d < 32; d <<= 1) {
        double nv = __shfl_up_sync(0xffffffffu, x, d);
        if (lane >= d) x += nv;
    }
    __shared__ double wsum[32];
    if (lane == 31) wsum[wid] = x;
    __syncthreads();
    if (wid == 0) {
        double w = wsum[lane];
        #pragma unroll
        for (int d = 1; d < 32; d <<= 1) {
            double nv = __shfl_up_sync(0xffffffffu, w, d);
            if (lane >= d) w += nv;
        }
        wsum[lane] = w;
    }
    __syncthreads();

    double base = (wid > 0) ? wsum[wid - 1] : 0.0;
    double incl = base + x;        // inclusive prefix of pair sums
    double excl = incl - pair;

    double neg = g_neg;
    double P0 = neg + excl + v0;
    double P1 = P0 + v1;

    double loss2 = 0.0;
    long long obs = c0 + c1;
    if (c0 > 0) loss2 += (double)c0 * log(P0);
    if (c1 > 0) loss2 += (double)c1 * log(P1);

    // block reduce (loss2, obs)
    #pragma unroll
    for (int d = 16; d; d >>= 1) {
        loss2 += __shfl_down_sync(0xffffffffu, loss2, d);
        obs   += __shfl_down_sync(0xffffffffu, obs, d);
    }
    __shared__ double sL[32];
    __shared__ long long sO[32];
    if (lane == 0) { sL[wid] = loss2; sO[wid] = obs; }
    __syncthreads();
    if (tid == 0) {
        double L = 0.0; long long O = 0;
        #pragma unroll
        for (int w = 0; w < 32; w++) { L += sL[w]; O += sO[w]; }
        double loss = (L - g_yhat) / (double)O;
        for (int j = 0; j < out_size; j++) out[j] = (float)loss;
    }
    __syncthreads();

    // self-clean for the next replay (graph replays reuse module state)
    for (int i = tid; i < NBINS; i += blockDim.x) g_bins[i] = 0ULL;
    if (tid == 0) { g_neg = 0.0; g_yhat = 0.0; }
}

extern "C" void kernel_launch(void* const* d_in, const int* in_sizes, int n_in,
                              void* d_out, int out_size)
{
    const float* Yhat = (const float*)d_in[0];
    const float* Y    = (const float*)d_in[1];
    int n = in_sizes[0];

    surv_hist<<<296, 512>>>(Yhat, Y, n);
    surv_final<<<1, 1024>>>((float*)d_out, out_size);
}

// round 5
// speedup vs baseline: 1.9236x; 1.9236x over previous
#include <cuda_runtime.h>

#define NBINS 2000
#define FRAC_SCALE 16777216.0f      /* 2^24 */
#define FRAC_INV_F (5.9604644775390625e-8f) /* 2^-24 */
#define SUM_MASK   0xFFFFFFFFFFULL  /* low 40 bits */

// Persistent scratch (zero-initialized at module load; finalize kernel re-zeroes
// for the next graph replay).
__device__ unsigned long long g_bins[NBINS];
__device__ double g_neg;    // sum of exp(Yhat) over Y<0
__device__ double g_yhat;   // sum of Yhat over Y>0 (loss1)

// ---------------------------------------------------------------------------
// Pass 1: histogram exp(Yhat) by time bin for events; accumulate negatives.
// One u64 shared atomic per positive element: packed = (1<<40) | round(e*2^24)
// ---------------------------------------------------------------------------
__global__ void __launch_bounds__(512) surv_hist(
    const float* __restrict__ Yhat, const float* __restrict__ Y, int n)
{
    __shared__ unsigned long long sBins[NBINS];
    for (int i = threadIdx.x; i < NBINS; i += blockDim.x) sBins[i] = 0ULL;
    __syncthreads();

    float negAcc = 0.f, yhatAcc = 0.f;

    const int n4 = n >> 2;
    const float4* Yh4 = (const float4*)Yhat;
    const float4* Y4  = (const float4*)Y;
    const int stride = gridDim.x * blockDim.x;

    for (int i = blockIdx.x * blockDim.x + threadIdx.x; i < n4; i += stride) {
        float4 yh = Yh4[i];
        float4 yy = Y4[i];
        float hv[4] = {yh.x, yh.y, yh.z, yh.w};
        float yv[4] = {yy.x, yy.y, yy.z, yy.w};
        #pragma unroll
        for (int k = 0; k < 4; k++) {
            float e = expf(hv[k]);
            if (yv[k] > 0.f) {
                int t = (int)yv[k];                      // 1..2000
                t = (t < 1) ? 1 : (t > NBINS ? NBINS : t);
                unsigned long long q = __float2ull_rn(e * FRAC_SCALE);
                atomicAdd(&sBins[t - 1], (1ULL << 40) | q);
                yhatAcc += hv[k];
            } else {
                negAcc += e;
            }
        }
    }

    // scalar tail
    if (blockIdx.x == 0 && threadIdx.x == 0) {
        for (int i = n4 << 2; i < n; i++) {
            float e = expf(Yhat[i]);
            float y = Y[i];
            if (y > 0.f) {
                int t = (int)y;
                t = (t < 1) ? 1 : (t > NBINS ? NBINS : t);
                unsigned long long q = __float2ull_rn(e * FRAC_SCALE);
                atomicAdd(&sBins[t - 1], (1ULL << 40) | q);
                yhatAcc += Yhat[i];
            } else {
                negAcc += e;
            }
        }
    }

    __syncthreads();

    // Flush shared histogram to global (deterministic integer adds)
    for (int i = threadIdx.x; i < NBINS; i += blockDim.x) {
        unsigned long long v = sBins[i];
        if (v) atomicAdd(&g_bins[i], v);
    }

    // Block-reduce negAcc / yhatAcc, one double atomic per block
    #pragma unroll
    for (int d = 16; d; d >>= 1) {
        negAcc  += __shfl_down_sync(0xffffffffu, negAcc,  d);
        yhatAcc += __shfl_down_sync(0xffffffffu, yhatAcc, d);
    }
    __shared__ float wNeg[32], wYh[32];
    int lane = threadIdx.x & 31, wid = threadIdx.x >> 5;
    if (lane == 0) { wNeg[wid] = negAcc; wYh[wid] = yhatAcc; }
    __syncthreads();
    if (wid == 0) {
        int nw = blockDim.x >> 5;
        float a = (lane < nw) ? wNeg[lane] : 0.f;
        float b = (lane < nw) ? wYh[lane] : 0.f;
        #pragma unroll
        for (int d = 16; d; d >>= 1) {
            a += __shfl_down_sync(0xffffffffu, a, d);
            b += __shfl_down_sync(0xffffffffu, b, d);
        }
        if (lane == 0) {
            atomicAdd(&g_neg,  (double)a);
            atomicAdd(&g_yhat, (double)b);
        }
    }
}

// ---------------------------------------------------------------------------
// Pass 2: exact u64 fixed-point inclusive scan (ALU pipe, no FP64), float logf
// per bin, float block reduce. FP64 only in ~33 final ops on thread 0.
// ---------------------------------------------------------------------------
__global__ void __launch_bounds__(1024) surv_final(float* out, int out_size)
{
    const int tid = threadIdx.x;
    const int lane = tid & 31, wid = tid >> 5;

    unsigned long long s0 = 0ULL, s1 = 0ULL;
    unsigned int c0 = 0u, c1 = 0u;
    int b0 = 2 * tid, b1 = 2 * tid + 1;
    if (b0 < NBINS) {
        unsigned long long p = g_bins[b0];
        s0 = p & SUM_MASK;
        c0 = (unsigned int)(p >> 40);
    }
    if (b1 < NBINS) {
        unsigned long long p = g_bins[b1];
        s1 = p & SUM_MASK;
        c1 = (unsigned int)(p >> 40);
    }

    unsigned long long pair = s0 + s1;

    // negative-arm sum in fixed point (computed once, shared)
    __shared__ unsigned long long sNegQ;
    if (tid == 0) sNegQ = (unsigned long long)(g_neg * (double)FRAC_SCALE + 0.5);

    // inclusive scan of `pair` across 1024 threads (exact integer)
    unsigned long long x = pair;
    #pragma unroll
    for (int d = 1; d < 32; d <<= 1) {
        unsigned long long nv = __shfl_up_sync(0xffffffffu, x, d);
        if (lane >= d) x += nv;
    }
    __shared__ unsigned long long wsum[32];
    if (lane == 31) wsum[wid] = x;
    __syncthreads();
    if (wid == 0) {
        unsigned long long w = wsum[lane];
        #pragma unroll
        for (int d = 1; d < 32; d <<= 1) {
            unsigned long long nv = __shfl_up_sync(0xffffffffu, w, d);
            if (lane >= d) w += nv;
        }
        wsum[lane] = w;
    }
    __syncthreads();

    unsigned long long base = (wid > 0) ? wsum[wid - 1] : 0ULL;
    unsigned long long incl = base + x;     // inclusive prefix of pair sums
    unsigned long long excl = incl - pair;

    unsigned long long P0q = sNegQ + excl + s0;
    unsigned long long P1q = P0q + s1;

    // float log of fixed-point prefix (MUFU path, fast)
    float loss2 = 0.f;
    unsigned int obs = c0 + c1;
    if (c0 > 0u) loss2 += (float)c0 * __logf((float)(unsigned long long)P0q * FRAC_INV_F);
    if (c1 > 0u) loss2 += (float)c1 * __logf((float)(unsigned long long)P1q * FRAC_INV_F);

    // block reduce (loss2 float, obs int)
    #pragma unroll
    for (int d = 16; d; d >>= 1) {
        loss2 += __shfl_down_sync(0xffffffffu, loss2, d);
        obs   += __shfl_down_sync(0xffffffffu, obs, d);
    }
    __shared__ float sL[32];
    __shared__ unsigned int sO[32];
    if (lane == 0) { sL[wid] = loss2; sO[wid] = obs; }
    __syncthreads();
    if (tid == 0) {
        double L = 0.0; unsigned long long O = 0;
        #pragma unroll
        for (int w = 0; w < 32; w++) { L += (double)sL[w]; O += sO[w]; }
        double loss = (L - g_yhat) / (double)O;
        for (int j = 0; j < out_size; j++) out[j] = (float)loss;
    }
    __syncthreads();

    // self-clean for the next replay
    for (int i = tid; i < NBINS; i += blockDim.x) g_bins[i] = 0ULL;
    if (tid == 0) { g_neg = 0.0; g_yhat = 0.0; }
}

extern "C" void kernel_launch(void* const* d_in, const int* in_sizes, int n_in,
                              void* d_out, int out_size)
{
    const float* Yhat = (const float*)d_in[0];
    const float* Y    = (const float*)d_in[1];
    int n = in_sizes[0];

    surv_hist<<<296, 512>>>(Yhat, Y, n);
    surv_final<<<1, 1024>>>((float*)d_out, out_size);
}